// round 1
// baseline (speedup 1.0000x reference)
#include <cuda_runtime.h>
#include <cstdint>

#define COLS   24576
#define V4     (COLS / 4)      // 6144 float4 per row
#define NBINS  8192            // top-13 bits of monotonic key
#define NT     512             // threads per CTA
#define BPT    (NBINS / NT)    // 16 bins per thread in the scan
#define CAP    1024            // candidate buffer capacity

// Order-preserving float->uint key: larger float => larger key.
__device__ __forceinline__ uint32_t fkey(float f) {
    uint32_t u = __float_as_uint(f);
    return (u & 0x80000000u) ? ~u : (u | 0x80000000u);
}

__global__ __launch_bounds__(NT) void topk_scatter_kernel(
    const float* __restrict__ z,
    const int*   __restrict__ kin,
    float*       __restrict__ out)
{
    __shared__ uint32_t hist[NBINS];       // 32 KB
    __shared__ uint32_t candKey[CAP];      // 4 KB
    __shared__ uint16_t candIdx[CAP];      // 2 KB (idx < 24576 fits u16)
    __shared__ uint32_t scanBuf[NT];       // 2 KB
    __shared__ uint32_t s_binB, s_above, s_cnt, s_thr, s_cut;

    const int tid = threadIdx.x;
    const int row = blockIdx.x;
    const uint32_t k = (uint32_t)(kin ? *kin : 64);

    const float4* zr = reinterpret_cast<const float4*>(z) + (size_t)row * V4;
    float4*       orw = reinterpret_cast<float4*>(out)    + (size_t)row * V4;

    for (int i = tid; i < NBINS; i += NT) hist[i] = 0;
    if (tid == 0) { s_cnt = 0; s_thr = 0xFFFFFFFFu; s_cut = 0; }
    __syncthreads();

    // ---- Pass 1: 13-bit histogram (HBM read #1) ----
    for (int i = tid; i < V4; i += NT) {
        float4 v = zr[i];
        atomicAdd(&hist[fkey(v.x) >> 19], 1u);
        atomicAdd(&hist[fkey(v.y) >> 19], 1u);
        atomicAdd(&hist[fkey(v.z) >> 19], 1u);
        atomicAdd(&hist[fkey(v.w) >> 19], 1u);
    }
    __syncthreads();

    // ---- Block suffix scan to locate the rank-k bin ----
    const int base = tid * BPT;
    uint32_t s = 0;
    #pragma unroll
    for (int j = 0; j < BPT; j++) s += hist[base + j];
    scanBuf[tid] = s;
    __syncthreads();
    for (int off = 1; off < NT; off <<= 1) {
        uint32_t add = (tid + off < NT) ? scanBuf[tid + off] : 0u;
        __syncthreads();
        scanBuf[tid] += add;
        __syncthreads();
    }
    uint32_t incl = scanBuf[tid];
    uint32_t abv  = (tid + 1 < NT) ? scanBuf[tid + 1] : 0u;
    if (abv < k && incl >= k) {            // exactly one thread matches
        uint32_t a = abv;
        #pragma unroll
        for (int j = BPT - 1; j >= 0; j--) {
            uint32_t c = hist[base + j];
            if (a + c >= k) { s_binB = (uint32_t)(base + j); s_above = a; break; }
            a += c;
        }
    }
    __syncthreads();
    const uint32_t binB = s_binB;
    const uint32_t need = k - s_above;     // how many to take from bin binB

    // ---- Pass 2: collect candidates in the threshold bin (L2 read) ----
    for (int i = tid; i < V4; i += NT) {
        float4 v = zr[i];
        uint32_t k0 = fkey(v.x), k1 = fkey(v.y), k2 = fkey(v.z), k3 = fkey(v.w);
        uint32_t i4 = (uint32_t)(4 * i);
        if ((k0 >> 19) == binB) { uint32_t p = atomicAdd(&s_cnt, 1u); if (p < CAP) { candKey[p] = k0; candIdx[p] = (uint16_t)(i4 + 0); } }
        if ((k1 >> 19) == binB) { uint32_t p = atomicAdd(&s_cnt, 1u); if (p < CAP) { candKey[p] = k1; candIdx[p] = (uint16_t)(i4 + 1); } }
        if ((k2 >> 19) == binB) { uint32_t p = atomicAdd(&s_cnt, 1u); if (p < CAP) { candKey[p] = k2; candIdx[p] = (uint16_t)(i4 + 2); } }
        if ((k3 >> 19) == binB) { uint32_t p = atomicAdd(&s_cnt, 1u); if (p < CAP) { candKey[p] = k3; candIdx[p] = (uint16_t)(i4 + 3); } }
    }
    __syncthreads();
    const uint32_t n = min(s_cnt, (uint32_t)CAP);

    // ---- Exact rank among candidates: rank = (key desc, idx asc) ----
    // thr = min key among the `need` included candidates
    for (uint32_t j = tid; j < n; j += NT) {
        uint32_t kj = candKey[j], ij = candIdx[j];
        uint32_t r = 0;
        for (uint32_t m = 0; m < n; m++) {
            uint32_t km = candKey[m];
            r += (km > kj) || (km == kj && candIdx[m] < ij);
        }
        if (r < need) atomicMin(&s_thr, kj);
    }
    __syncthreads();
    const uint32_t thr = s_thr;
    // tie-break cutoff: largest included index among key == thr
    for (uint32_t j = tid; j < n; j += NT) {
        if (candKey[j] != thr) continue;
        uint32_t ij = candIdx[j];
        uint32_t r = 0;
        for (uint32_t m = 0; m < n; m++) {
            uint32_t km = candKey[m];
            r += (km > thr) || (km == thr && candIdx[m] < ij);
        }
        if (r < need) atomicMax(&s_cut, ij);
    }
    __syncthreads();
    const uint32_t cut = s_cut;

    // ---- Pass 3: scatter write (L2 read + HBM write) ----
    for (int i = tid; i < V4; i += NT) {
        float4 v = zr[i];
        uint32_t i4 = (uint32_t)(4 * i);
        uint32_t k0 = fkey(v.x), k1 = fkey(v.y), k2 = fkey(v.z), k3 = fkey(v.w);
        float4 o;
        o.x = (k0 > thr || (k0 == thr && (i4 + 0) <= cut)) ? v.x : 0.0f;
        o.y = (k1 > thr || (k1 == thr && (i4 + 1) <= cut)) ? v.y : 0.0f;
        o.z = (k2 > thr || (k2 == thr && (i4 + 2) <= cut)) ? v.z : 0.0f;
        o.w = (k3 > thr || (k3 == thr && (i4 + 3) <= cut)) ? v.w : 0.0f;
        orw[i] = o;
    }
}

extern "C" void kernel_launch(void* const* d_in, const int* in_sizes, int n_in,
                              void* d_out, int out_size) {
    const float* z   = (const float*)d_in[0];
    const int*   kin = (n_in >= 2) ? (const int*)d_in[1] : nullptr;
    float*       out = (float*)d_out;
    int rows = in_sizes[0] / COLS;   // 8192
    topk_scatter_kernel<<<rows, NT>>>(z, kin, out);
}